// round 16
// baseline (speedup 1.0000x reference)
#include <cuda_runtime.h>
#include <cuda_fp16.h>
#include <math.h>
#include <stdint.h>

// Shapes (fixed by the problem)
#define Bq 4
#define Nq 2048
#define Eq 768
#define Hq 12
#define Mq 256
#define Dhq 64
#define Fq 3072
#define ROWS (Bq*Hq*Nq)   // 98304
#define BN (Bq*Nq)        // 8192

#define RATIO 0.0625f            // M^-0.5
#define REPS  6.25e-6f           // RATIO * EPS(1e-4)
#define XSCL  0.35355339059327373f  // Dh^-0.25

#define CTX_S 4                   // ctx split-K chunks
#define CH    (Bq*Hq*Mq*128)      // per-chunk ctxf stride (floats)
#define M2STR ((size_t)BN*Eq)     // mlp2 partial stride

// Scratch (device globals; allocation-free)
__device__ __half g_hsh[ROWS*Dhq];    // half(y*XSCL), head layout
__device__ __half g_hTh[Bq*Hq*128*Nq];// per head: [128 x 2048]: rows 0-63 hsh^T, row 64 ones, rest 0
__device__ __half g_projh[Mq*Dhq];    // half proj
__device__ __half g_uh[ROWS*Mq];      // u in half
__device__ __half g_qph[ROWS*Mq];     // half(e*RATIO + REPS)
__device__ __half g_kphT[ROWS*Mq];    // per head transposed: [m][n]
__device__ float  g_diag[ROWS];
__device__ float  g_stabq[ROWS];
__device__ float  g_scale[ROWS];
__device__ float  g_ctxf[CTX_S*CH];   // ctx split-K partials: [chunk][head][m][128]
__device__ __half g_ctxTh[Bq*Hq*128*Mq];  // per head [128 x 256]: d<64 ctx^T, row 64 ksum, rest 0
__device__ float  g_x1[BN*Eq];        // x + attn
__device__ __half g_h2h[BN*Eq];       // LN2 out (half)
__device__ __half g_midh[BN*Fq];      // gelu(h2@W1+b1) (half)
__device__ float  g_m2p[2*M2STR];     // mlp2 split-K partials
__device__ __half g_w1h[Fq*Eq];       // W1^T half
__device__ __half g_w2h[Eq*Fq];       // W2^T half

// ======================= helpers =======================
__device__ __forceinline__ uint32_t s2u(const void* p){
    uint32_t a;
    asm("{ .reg .u64 t; cvta.to.shared.u64 t, %1; cvt.u32.u64 %0, t; }":"=r"(a):"l"(p));
    return a;
}
__device__ __forceinline__ void cpasync16(uint32_t sa, const void* ga){
    asm volatile("cp.async.cg.shared.global [%0], [%1], 16;" :: "r"(sa), "l"(ga));
}
__device__ __forceinline__ void mma16(float* d, const uint32_t* a, const uint32_t* b){
    asm volatile("mma.sync.aligned.m16n8k16.row.col.f32.f16.f16.f32 "
        "{%0,%1,%2,%3}, {%4,%5,%6,%7}, {%8,%9}, {%0,%1,%2,%3};"
        : "+f"(d[0]),"+f"(d[1]),"+f"(d[2]),"+f"(d[3])
        : "r"(a[0]),"r"(a[1]),"r"(a[2]),"r"(a[3]),"r"(b[0]),"r"(b[1]));
}
#define LDSM4(r0,r1,r2,r3,ad) \
    asm volatile("ldmatrix.sync.aligned.m8n8.x4.shared.b16 {%0,%1,%2,%3}, [%4];" \
        : "=r"(r0),"=r"(r1),"=r"(r2),"=r"(r3) : "r"(ad))

// ---------------- LN1: warp-per-token (hsh + diag only) ----------------
__global__ void k_ln1(const float* __restrict__ x, const float* __restrict__ g,
                      const float* __restrict__ b) {
    int warp = (blockIdx.x*256 + threadIdx.x) >> 5;   // token 0..8191
    int l = threadIdx.x & 31;
    const float4* xr = (const float4*)(x + (size_t)warp*Eq);
    float4 v[6];
    float s1 = 0.f, s2 = 0.f;
    #pragma unroll
    for (int i=0;i<6;i++){
        v[i] = xr[l + 32*i];
        s1 += v[i].x+v[i].y+v[i].z+v[i].w;
        s2 += v[i].x*v[i].x+v[i].y*v[i].y+v[i].z*v[i].z+v[i].w*v[i].w;
    }
    #pragma unroll
    for (int o=16;o;o>>=1){ s1+=__shfl_xor_sync(~0u,s1,o); s2+=__shfl_xor_sync(~0u,s2,o); }
    float m = s1*(1.f/Eq);
    float rstd = rsqrtf(s2*(1.f/Eq) - m*m + 1e-5f);
    int bb = warp>>11, n = warp&2047;
    #pragma unroll
    for (int i=0;i<6;i++){
        int f = l + 32*i;
        int e = f*4;
        float4 gv = ((const float4*)g)[f];
        float4 bv = ((const float4*)b)[f];
        float4 y;
        y.x = (v[i].x-m)*rstd*gv.x + bv.x;
        y.y = (v[i].y-m)*rstd*gv.y + bv.y;
        y.z = (v[i].z-m)*rstd*gv.z + bv.z;
        y.w = (v[i].w-m)*rstd*gv.w + bv.w;
        int hd = e>>6, d = e&63;
        size_t hi = ((size_t)(bb*Hq+hd)*Nq + n)*Dhq + d;
        *(__half2*)&g_hsh[hi]   = __floats2half2_rn(y.x*XSCL, y.y*XSCL);
        *(__half2*)&g_hsh[hi+2] = __floats2half2_rn(y.z*XSCL, y.w*XSCL);
        float yy = y.x*y.x + y.y*y.y + y.z*y.z + y.w*y.w;
        #pragma unroll
        for (int o=8;o;o>>=1) yy += __shfl_xor_sync(~0u,yy,o);
        if ((l&15)==0){
            int hd2 = 2*i + (l>>4);
            g_diag[(bb*Hq+hd2)*Nq + n] = 0.0625f * yy;
        }
    }
}

// ---------------- LN2: warp-per-token, half out ----------------
__global__ void k_ln2(const float* __restrict__ g, const float* __restrict__ b) {
    int warp = (blockIdx.x*256 + threadIdx.x) >> 5;
    int l = threadIdx.x & 31;
    const float4* xr = (const float4*)(g_x1 + (size_t)warp*Eq);
    float4 v[6];
    float s1 = 0.f, s2 = 0.f;
    #pragma unroll
    for (int i=0;i<6;i++){
        v[i] = xr[l + 32*i];
        s1 += v[i].x+v[i].y+v[i].z+v[i].w;
        s2 += v[i].x*v[i].x+v[i].y*v[i].y+v[i].z*v[i].z+v[i].w*v[i].w;
    }
    #pragma unroll
    for (int o=16;o;o>>=1){ s1+=__shfl_xor_sync(~0u,s1,o); s2+=__shfl_xor_sync(~0u,s2,o); }
    float m = s1*(1.f/Eq);
    float rstd = rsqrtf(s2*(1.f/Eq) - m*m + 1e-5f);
    __half* hr = g_h2h + (size_t)warp*Eq;
    #pragma unroll
    for (int i=0;i<6;i++){
        int f = l + 32*i;
        float4 gv = ((const float4*)g)[f];
        float4 bv = ((const float4*)b)[f];
        float4 y;
        y.x = (v[i].x-m)*rstd*gv.x + bv.x;
        y.y = (v[i].y-m)*rstd*gv.y + bv.y;
        y.z = (v[i].z-m)*rstd*gv.z + bv.z;
        y.w = (v[i].w-m)*rstd*gv.w + bv.w;
        *(__half2*)&hr[f*4]   = __floats2half2_rn(y.x, y.y);
        *(__half2*)&hr[f*4+2] = __floats2half2_rn(y.z, y.w);
    }
}

__global__ void k_roundproj(const float* __restrict__ proj) {
    int i = blockIdx.x*256 + threadIdx.x;
    g_projh[i] = __float2half(proj[i]);
}

// ---------------- row max (stab_q) over half u ----------------
__global__ void k_stabq() {
    int row = blockIdx.x*8 + (threadIdx.x>>5);
    int l = threadIdx.x & 31;
    const __half2* u2 = (const __half2*)(g_uh + (size_t)row*256);
    __half2 m2 = u2[l*4];
    m2 = __hmax2(m2, u2[l*4+1]);
    m2 = __hmax2(m2, u2[l*4+2]);
    m2 = __hmax2(m2, u2[l*4+3]);
    float m = fmaxf(__low2float(m2), __high2float(m2));
    #pragma unroll
    for (int o=16;o;o>>=1) m = fmaxf(m, __shfl_xor_sync(~0u,m,o));
    if (l==0) g_stabq[row] = m;
}

// ---------------- merged: per-head max + per-row scale ----------------
__global__ void k_stabk_scale() {
    int g = blockIdx.x, tid = threadIdx.x;   // 48 blocks, 256 threads
    __shared__ float red[8];
    __shared__ float sk;
    float sq[8];
    float m = -1e30f;
    #pragma unroll
    for (int j=0;j<8;j++){ sq[j] = g_stabq[g*2048 + tid + j*256]; m = fmaxf(m, sq[j]); }
    #pragma unroll
    for (int o=16;o;o>>=1) m = fmaxf(m, __shfl_xor_sync(~0u,m,o));
    if ((tid&31)==0) red[tid>>5] = m;
    __syncthreads();
    if (tid==0){
        float t = red[0];
        #pragma unroll
        for (int i=1;i<8;i++) t = fmaxf(t, red[i]);
        sk = t;
    }
    __syncthreads();
    float s = sk;
    #pragma unroll
    for (int j=0;j<8;j++)
        g_scale[g*2048 + tid + j*256] = RATIO * __expf(sq[j] - s);
}

// ---------------- qp (half) + kp^T (half, transposed) from half u, one pass ----------------
__global__ void k_qk_exp() {
    __shared__ float t[32][33];
    int g = blockIdx.z, m0 = blockIdx.x*32, n0 = blockIdx.y*32;
    int x = threadIdx.x, y = threadIdx.y;   // block (32,8)
    #pragma unroll
    for (int i=0;i<32;i+=8){
        int n = n0 + y + i;
        size_t ro = ((size_t)g*2048 + n)*256;
        float uv = __half2float(g_uh[ro + m0 + x]);
        float dg = g_diag[g*2048+n], sq = g_stabq[g*2048+n], sc = g_scale[g*2048+n];
        float e = __expf(uv - dg - sq);
        g_qph[ro + m0 + x] = __float2half(fmaf(e, RATIO, REPS));
        t[y+i][x] = fmaf(e, sc, REPS);            // kv at [n_loc][m_loc]
    }
    __syncthreads();
    #pragma unroll
    for (int i=0;i<32;i+=8){
        int m = m0 + y + i;
        g_kphT[((size_t)g*256 + m)*2048 + n0 + x] = __float2half(t[x][y+i]);
    }
}

// ---------------- hTh: per head [128 x 2048]: rows 0-63 = hsh^T ----------------
__global__ void k_hT() {
    __shared__ __half t[32][33];
    int g = blockIdx.z, d0 = blockIdx.x*32, n0 = blockIdx.y*32;
    int x = threadIdx.x, y = threadIdx.y;   // block (32,8)
    #pragma unroll
    for (int i=0;i<32;i+=8)
        t[y+i][x] = g_hsh[((size_t)g*2048 + n0+y+i)*64 + d0 + x];
    __syncthreads();
    #pragma unroll
    for (int i=0;i<32;i+=8)
        g_hTh[(size_t)g*128*2048 + (size_t)(d0+y+i)*2048 + n0 + x] = t[x][y+i];
}
__global__ void k_hT2() {
    int g = blockIdx.x, r2 = blockIdx.y;    // r2 0..63
    __half val = (r2==0) ? __float2half(1.f) : __float2half(0.f);
    __half* base = g_hTh + (size_t)g*128*2048 + (size_t)(64+r2)*2048;
    for (int c = threadIdx.x; c < 2048; c += 256) base[c] = val;
}

// ---------------- ctxf partial sums -> ctxTh (half [d][m], scaled) ----------------
__global__ void k_ctx2half() {
    __shared__ float t[32][33];
    int g = blockIdx.z, m0 = blockIdx.y*32, d0 = blockIdx.x*32;
    int x = threadIdx.x, y = threadIdx.y;   // block (32,8)
    #pragma unroll
    for (int i=0;i<32;i+=8){
        size_t base = (size_t)g*256*128 + (size_t)(m0+y+i)*128 + d0 + x;
        float v = g_ctxf[base];
        #pragma unroll
        for (int s=1;s<CTX_S;s++) v += g_ctxf[base + (size_t)s*CH];
        t[y+i][x] = v;   // [m_loc][d_loc]
    }
    __syncthreads();
    #pragma unroll
    for (int i=0;i<32;i+=8){
        int d = d0 + y + i;
        float v = t[x][y+i];
        if (d < 64) v *= (1.0f/XSCL);
        g_ctxTh[(size_t)g*128*256 + (size_t)d*256 + m0 + x] = __float2half(v);
    }
}

// ---------------- mlp2 merge: out = p0 + p1 + b2 + x1 ----------------
__global__ void k_m2merge(const float* __restrict__ b2, float* __restrict__ out) {
    size_t i4 = ((size_t)blockIdx.x*256 + threadIdx.x)*4;
    int col = (int)(i4 % Eq);
    float4 p0 = *(const float4*)&g_m2p[i4];
    float4 p1 = *(const float4*)&g_m2p[M2STR + i4];
    float4 rv = *(const float4*)&g_x1[i4];
    float4 bv = *(const float4*)&b2[col];
    float4 v;
    v.x = p0.x + p1.x + rv.x + bv.x;
    v.y = p0.y + p1.y + rv.y + bv.y;
    v.z = p0.z + p1.z + rv.z + bv.z;
    v.w = p0.w + p1.w + rv.w + bv.w;
    *(float4*)&out[i4] = v;
}

// ---------------- transpose weights to half ----------------
__global__ void k_transposeh(const float* __restrict__ in, __half* __restrict__ out,
                             int R, int C) {
    __shared__ float t[32][33];
    int bx = blockIdx.x*32, by = blockIdx.y*32;
    int x = threadIdx.x, y = threadIdx.y;
    #pragma unroll
    for (int i=0;i<32;i+=8)
        t[y+i][x] = in[(size_t)(by+y+i)*C + bx+x];
    __syncthreads();
    #pragma unroll
    for (int i=0;i<32;i+=8)
        out[(size_t)(bx+y+i)*R + by+x] = __float2half(t[x][y+i]);
}

// ================= f16 mma.sync GEMM (ldmatrix, 3-stage, 1 sync/iter) =================
// EPI 0: Ch=half(gelu(acc+bias)). EPI 2: Ch=half(acc).
// EPI 3: attention: col 64 = denom; C = resid + num/den.
// EPI 5: mlp2 split-K: plain store into partial buffer C[chunk][row][col].
// EPI 6: ctx split-K: plain store into partial buffer C[chunk][head][m][128].
#define STB 80                        // smem row stride bytes (40 halves)
#define STAGE_A 10240                 // 128 rows * 80 B
#define STAGE   (2*STAGE_A)           // 20480
#define GSMEM_BYTES (3*STAGE)         // 61440 B

template<int EPI>
__global__ __launch_bounds__(256, 2) void k_gemm_h(
        const __half* __restrict__ A, int lda, size_t strA,
        const __half* __restrict__ Bt, int ldb, size_t strB,
        int klen,
        const float* __restrict__ bias,
        const float* __restrict__ resid,
        float* __restrict__ C, __half* __restrict__ Ch, int ldc) {
    extern __shared__ __align__(16) char dsm[];
    uint32_t smb = s2u(dsm);
    int tid = threadIdx.x, wid = tid>>5, lane = tid&31;
    int wm = (wid&1)*64, wn = (wid>>1)*32;
    int r = lane>>2, cq = lane&3;
    int z = blockIdx.z;
    int zh = z, zc = 0;
    if (EPI == 5){ zh = 0; zc = z; }
    if (EPI == 6){ zh = z>>2; zc = z&3; }

    int rbase = blockIdx.y*128, cbase = (EPI==6) ? 0 : blockIdx.x*128;
    const __half* Ag = A  + zh*strA + (size_t)zc*klen + (size_t)rbase*lda;
    const __half* Bg = Bt + zh*strB + (size_t)zc*klen + (size_t)cbase*ldb;
    int KT = klen >> 5;

    uint32_t a_ldsm_base = (uint32_t)((wm + (lane&7) + ((lane>>3)&1)*8)*STB + ((lane>>4)&1)*16);
    uint32_t b_ldsm_base = (uint32_t)((wn + (lane&7) + ((lane>>4)&1)*8)*STB + ((lane>>3)&1)*16);

    float acc[4][4][4];
    #pragma unroll
    for (int i=0;i<4;i++)
        #pragma unroll
        for (int j=0;j<4;j++)
            #pragma unroll
            for (int k=0;k<4;k++) acc[i][j][k]=0.f;

    #define LOAD_STAGE(s, kt) do { \
        uint32_t _ab = smb + (uint32_t)((s)*STAGE); \
        uint32_t _bb = _ab + STAGE_A; \
        const __half* _Ag = Ag + (kt)*32; \
        const __half* _Bg = Bg + (kt)*32; \
        _Pragma("unroll") \
        for (int _t=0;_t<2;_t++){ \
            int _q = tid + _t*256; int _r = _q>>2, _c = _q&3; \
            cpasync16(_ab + (uint32_t)(_r*STB + _c*16), _Ag + (size_t)_r*lda + _c*8); \
            cpasync16(_bb + (uint32_t)(_r*STB + _c*16), _Bg + (size_t)_r*ldb + _c*8); \
        } \
        asm volatile("cp.async.commit_group;" ::: "memory"); \
    } while(0)

    LOAD_STAGE(0, 0);
    if (KT > 1) LOAD_STAGE(1, 1);
    int cur = 0;
    for (int kt=0; kt<KT; kt++){
        if (kt+1 < KT) asm volatile("cp.async.wait_group 1;" ::: "memory");
        else           asm volatile("cp.async.wait_group 0;" ::: "memory");
        __syncthreads();
        if (kt+2 < KT){
            int nxt = cur+2; if (nxt>=3) nxt-=3;
            LOAD_STAGE(nxt, kt+2);
        }
        uint32_t ab = smb + (uint32_t)(cur*STAGE) + a_ldsm_base;
        uint32_t bb = smb + (uint32_t)(cur*STAGE) + STAGE_A + b_ldsm_base;
        #pragma unroll
        for (int ks=0; ks<2; ks++){
            uint32_t a[4][4], b[2][4];
            #pragma unroll
            for (int mf=0; mf<4; mf++)
                LDSM4(a[mf][0],a[mf][1],a[mf][2],a[mf][3], ab + mf*16*STB + ks*32);
            #pragma unroll
            for (int p=0; p<2; p++)
                LDSM4(b[p][0],b[p][1],b[p][2],b[p][3], bb + p*16*STB + ks*32);
            #pragma unroll
            for (int mf=0; mf<4; mf++)
                #pragma unroll
                for (int nf=0; nf<4; nf++)
                    mma16(acc[mf][nf], a[mf], &b[nf>>1][(nf&1)*2]);
        }
        cur = (cur==2) ? 0 : cur+1;
    }
    #undef LOAD_STAGE

    // Epilogue: two 64-row halves staged through smem (stride 132)
    float* stg = (float*)dsm;
    #pragma unroll 1
    for (int h=0; h<2; h++){
        __syncthreads();
        if ((wid&1) == h){
            #pragma unroll
            for (int mf=0; mf<4; mf++)
                #pragma unroll
                for (int nf=0; nf<4; nf++){
                    int row = mf*16 + r, col = wn + nf*8 + 2*cq;
                    *(float2*)&stg[row*132 + col]     = make_float2(acc[mf][nf][0], acc[mf][nf][1]);
                    *(float2*)&stg[(row+8)*132 + col] = make_float2(acc[mf][nf][2], acc[mf][nf][3]);
                }
        }
        __syncthreads();
        #pragma unroll
        for (int t=0;t<8;t++){
            int q = tid + t*256; int row = q>>5, c4 = (q&31)*4;
            int col = cbase + c4;
            if (EPI == 3){
                if (c4 < 64){
                    float4 v = *(const float4*)&stg[row*132 + c4];
                    float dinv = 1.f / stg[row*132 + 64];
                    int bb2 = zh/12, hd = zh%12;
                    int n = rbase + h*64 + row;
                    size_t oi = ((size_t)(bb2*2048 + n))*768 + hd*64 + c4;
                    float4 rv = *(const float4*)&resid[oi];
                    v.x = rv.x + v.x*dinv; v.y = rv.y + v.y*dinv;
                    v.z = rv.z + v.z*dinv; v.w = rv.w + v.w*dinv;
                    *(float4*)&C[oi] = v;
                }
            } else if (EPI == 6){
                float4 v = *(const float4*)&stg[row*132 + c4];
                size_t oi = (size_t)zc*CH + (size_t)zh*256*128 + (size_t)(rbase + h*64 + row)*128 + c4;
                *(float4*)&C[oi] = v;
            } else if (EPI == 5){
                float4 v = *(const float4*)&stg[row*132 + c4];
                size_t oi = (size_t)zc*M2STR + (size_t)(rbase + h*64 + row)*ldc + col;
                *(float4*)&C[oi] = v;
            } else if (EPI == 2){
                float4 v = *(const float4*)&stg[row*132 + c4];
                size_t oi = (size_t)(rbase + h*64 + row)*ldc + col;
                *reinterpret_cast<__half2*>(Ch + oi)     = __floats2half2_rn(v.x, v.y);
                *reinterpret_cast<__half2*>(Ch + oi + 2) = __floats2half2_rn(v.z, v.w);
            } else {
                float4 v = *(const float4*)&stg[row*132 + c4];
                size_t oi = (size_t)(rbase + h*64 + row)*ldc + col;
                // EPI 0: gelu + bias -> half
                v.x += bias[col+0]; v.y += bias[col+1]; v.z += bias[col+2]; v.w += bias[col+3];
                v.x = 0.5f*v.x*(1.f+erff(v.x*0.70710678118654752f));
                v.y = 0.5f*v.y*(1.f+erff(v.y*0.70710678118654752f));
                v.z = 0.5f*v.z*(1.f+erff(v.z*0.70710678118654752f));
                v.w = 0.5f*v.w*(1.f+erff(v.w*0.70710678118654752f));
                *reinterpret_cast<__half2*>(Ch + oi)     = __floats2half2_rn(v.x, v.y);
                *reinterpret_cast<__half2*>(Ch + oi + 2) = __floats2half2_rn(v.z, v.w);
            }
        }
    }
}

extern "C" void kernel_launch(void* const* d_in, const int* in_sizes, int n_in,
                              void* d_out, int out_size) {
    const float* x    = (const float*)d_in[0];
    const float* proj = (const float*)d_in[1];
    const float* ln1g = (const float*)d_in[2];
    const float* ln1b = (const float*)d_in[3];
    const float* ln2g = (const float*)d_in[4];
    const float* ln2b = (const float*)d_in[5];
    const float* W1   = (const float*)d_in[6];
    const float* b1   = (const float*)d_in[7];
    const float* W2   = (const float*)d_in[8];
    const float* b2   = (const float*)d_in[9];
    float* out = (float*)d_out;

    cudaFuncSetAttribute(k_gemm_h<0>, cudaFuncAttributeMaxDynamicSharedMemorySize, GSMEM_BYTES);
    cudaFuncSetAttribute(k_gemm_h<2>, cudaFuncAttributeMaxDynamicSharedMemorySize, GSMEM_BYTES);
    cudaFuncSetAttribute(k_gemm_h<3>, cudaFuncAttributeMaxDynamicSharedMemorySize, GSMEM_BYTES);
    cudaFuncSetAttribute(k_gemm_h<5>, cudaFuncAttributeMaxDynamicSharedMemorySize, GSMEM_BYTES);
    cudaFuncSetAttribute(k_gemm_h<6>, cudaFuncAttributeMaxDynamicSharedMemorySize, GSMEM_BYTES);

    __half* w1h;  cudaGetSymbolAddress((void**)&w1h,  g_w1h);
    __half* w2h;  cudaGetSymbolAddress((void**)&w2h,  g_w2h);
    __half* h2h;  cudaGetSymbolAddress((void**)&h2h,  g_h2h);
    __half* midh; cudaGetSymbolAddress((void**)&midh, g_midh);
    __half* hsh;  cudaGetSymbolAddress((void**)&hsh,  g_hsh);
    __half* prjh; cudaGetSymbolAddress((void**)&prjh, g_projh);
    __half* qph;  cudaGetSymbolAddress((void**)&qph,  g_qph);
    __half* kpht; cudaGetSymbolAddress((void**)&kpht, g_kphT);
    __half* hth;  cudaGetSymbolAddress((void**)&hth,  g_hTh);
    __half* ctxh; cudaGetSymbolAddress((void**)&ctxh, g_ctxTh);
    __half* uh;   cudaGetSymbolAddress((void**)&uh,   g_uh);
    float* ctxf;  cudaGetSymbolAddress((void**)&ctxf, g_ctxf);
    float* m2p;   cudaGetSymbolAddress((void**)&m2p,  g_m2p);
    float* x1;    cudaGetSymbolAddress((void**)&x1,   g_x1);

    // input-only prep
    k_transposeh<<<dim3(Fq/32, Eq/32), dim3(32,8)>>>(W1, w1h, Eq, Fq);
    k_transposeh<<<dim3(Eq/32, Fq/32), dim3(32,8)>>>(W2, w2h, Fq, Eq);
    k_roundproj<<<Mq*Dhq/256, 256>>>(proj);

    k_ln1<<<BN/8, 256>>>(x, ln1g, ln1b);
    // u = hsh @ projh^T : [98304 x 64] @ [64 x 256] -> half u
    k_gemm_h<2><<<dim3(Mq/128, ROWS/128), 256, GSMEM_BYTES>>>(
        hsh, Dhq, 0, prjh, Dhq, 0, Dhq, nullptr, nullptr, nullptr, uh, Mq);
    k_stabq<<<ROWS/8, 256>>>();
    k_stabk_scale<<<Bq*Hq, 256>>>();
    k_qk_exp<<<dim3(Mq/32, Nq/32, Bq*Hq), dim3(32,8)>>>();
    k_hT<<<dim3(2, Nq/32, Bq*Hq), dim3(32,8)>>>();
    k_hT2<<<dim3(Bq*Hq, 64), 256>>>();
    // ctx GEMM split-K=4, disjoint partials: per head [256 x 2048] @ [2048 x 128]
    k_gemm_h<6><<<dim3(1, 2, Bq*Hq*CTX_S), 256, GSMEM_BYTES>>>(
        kpht, Nq, (size_t)Mq*Nq, hth, Nq, (size_t)128*Nq, Nq/CTX_S, nullptr, nullptr, ctxf, nullptr, 0);
    k_ctx2half<<<dim3(4, 8, Bq*Hq), dim3(32,8)>>>();
    // attn: per head [2048 x 256] @ [256 x 128(ctx^T|ksum|0)] -> x1 = x + num/den
    k_gemm_h<3><<<dim3(1, Nq/128, Bq*Hq), 256, GSMEM_BYTES>>>(
        qph, Mq, (size_t)Nq*Mq, ctxh, Mq, (size_t)128*Mq, Mq, nullptr, x, x1, nullptr, 0);
    k_ln2<<<BN/8, 256>>>(ln2g, ln2b);

    // MLP GEMM1: [8192x768]@[768x3072] -> midh (gelu, half)
    k_gemm_h<0><<<dim3(Fq/128, BN/128), 256, GSMEM_BYTES>>>(
        h2h, Eq, 0, w1h, Eq, 0, Eq, b1, nullptr, nullptr, midh, Fq);
    // MLP GEMM2 split-K=2, disjoint partials, then merge with bias + residual
    k_gemm_h<5><<<dim3(Eq/128, BN/128, 2), 256, GSMEM_BYTES>>>(
        midh, Fq, 0, w2h, Fq, 0, Fq/2, nullptr, nullptr, m2p, nullptr, Eq);
    k_m2merge<<<BN*Eq/1024, 256>>>(b2, out);
}

// round 17
// speedup vs baseline: 1.0208x; 1.0208x over previous
#include <cuda_runtime.h>
#include <cuda_fp16.h>
#include <math.h>
#include <stdint.h>

// Shapes (fixed by the problem)
#define Bq 4
#define Nq 2048
#define Eq 768
#define Hq 12
#define Mq 256
#define Dhq 64
#define Fq 3072
#define ROWS (Bq*Hq*Nq)   // 98304
#define BN (Bq*Nq)        // 8192

#define RATIO 0.0625f            // M^-0.5
#define REPS  6.25e-6f           // RATIO * EPS(1e-4)
#define XSCL  0.35355339059327373f  // Dh^-0.25

#define CTX_S 4                   // ctx split-K chunks
#define CH    (Bq*Hq*Mq*128)      // per-chunk ctxf stride (floats)

// Scratch (device globals; allocation-free; zero-initialized at load)
__device__ __half g_hsh[ROWS*Dhq];    // half(y*XSCL), head layout
__device__ __half g_hTh[Bq*Hq*128*Nq];// per head [128 x 2048]: rows 0-63 hsh^T, row 64 ones,
                                      // rows 65-127 never written (stay zero from static init)
__device__ __half g_projh[Mq*Dhq];    // half proj
__device__ __half g_uh[ROWS*Mq];      // u in half
__device__ __half g_qph[ROWS*Mq];     // half(e*RATIO + REPS)
__device__ __half g_kphT[ROWS*Mq];    // per head transposed: [m][n]
__device__ float  g_diag[ROWS];
__device__ float  g_stabq[ROWS];
__device__ float  g_scale[ROWS];
__device__ float  g_ctxf[CTX_S*CH];   // ctx split-K partials: [chunk][head][m][128]
__device__ __half g_ctxTh[Bq*Hq*128*Mq];  // per head [128 x 256]: d<64 ctx^T, row 64 ksum
__device__ float  g_x1[BN*Eq];        // x + attn
__device__ __half g_h2h[BN*Eq];       // LN2 out (half)
__device__ __half g_midh[BN*Fq];      // gelu(h2@W1+b1) (half)
__device__ __half g_w1h[Fq*Eq];       // W1^T half
__device__ __half g_w2h[Eq*Fq];       // W2^T half

// ======================= helpers =======================
__device__ __forceinline__ uint32_t s2u(const void* p){
    uint32_t a;
    asm("{ .reg .u64 t; cvta.to.shared.u64 t, %1; cvt.u32.u64 %0, t; }":"=r"(a):"l"(p));
    return a;
}
__device__ __forceinline__ void cpasync16(uint32_t sa, const void* ga){
    asm volatile("cp.async.cg.shared.global [%0], [%1], 16;" :: "r"(sa), "l"(ga));
}
__device__ __forceinline__ void mma16(float* d, const uint32_t* a, const uint32_t* b){
    asm volatile("mma.sync.aligned.m16n8k16.row.col.f32.f16.f16.f32 "
        "{%0,%1,%2,%3}, {%4,%5,%6,%7}, {%8,%9}, {%0,%1,%2,%3};"
        : "+f"(d[0]),"+f"(d[1]),"+f"(d[2]),"+f"(d[3])
        : "r"(a[0]),"r"(a[1]),"r"(a[2]),"r"(a[3]),"r"(b[0]),"r"(b[1]));
}
#define LDSM4(r0,r1,r2,r3,ad) \
    asm volatile("ldmatrix.sync.aligned.m8n8.x4.shared.b16 {%0,%1,%2,%3}, [%4];" \
        : "=r"(r0),"=r"(r1),"=r"(r2),"=r"(r3) : "r"(ad))

// ---------------- LN1: warp-per-token (hsh + diag only) ----------------
__global__ void k_ln1(const float* __restrict__ x, const float* __restrict__ g,
                      const float* __restrict__ b) {
    int warp = (blockIdx.x*256 + threadIdx.x) >> 5;   // token 0..8191
    int l = threadIdx.x & 31;
    const float4* xr = (const float4*)(x + (size_t)warp*Eq);
    float4 v[6];
    float s1 = 0.f, s2 = 0.f;
    #pragma unroll
    for (int i=0;i<6;i++){
        v[i] = xr[l + 32*i];
        s1 += v[i].x+v[i].y+v[i].z+v[i].w;
        s2 += v[i].x*v[i].x+v[i].y*v[i].y+v[i].z*v[i].z+v[i].w*v[i].w;
    }
    #pragma unroll
    for (int o=16;o;o>>=1){ s1+=__shfl_xor_sync(~0u,s1,o); s2+=__shfl_xor_sync(~0u,s2,o); }
    float m = s1*(1.f/Eq);
    float rstd = rsqrtf(s2*(1.f/Eq) - m*m + 1e-5f);
    int bb = warp>>11, n = warp&2047;
    #pragma unroll
    for (int i=0;i<6;i++){
        int f = l + 32*i;
        int e = f*4;
        float4 gv = ((const float4*)g)[f];
        float4 bv = ((const float4*)b)[f];
        float4 y;
        y.x = (v[i].x-m)*rstd*gv.x + bv.x;
        y.y = (v[i].y-m)*rstd*gv.y + bv.y;
        y.z = (v[i].z-m)*rstd*gv.z + bv.z;
        y.w = (v[i].w-m)*rstd*gv.w + bv.w;
        int hd = e>>6, d = e&63;
        size_t hi = ((size_t)(bb*Hq+hd)*Nq + n)*Dhq + d;
        *(__half2*)&g_hsh[hi]   = __floats2half2_rn(y.x*XSCL, y.y*XSCL);
        *(__half2*)&g_hsh[hi+2] = __floats2half2_rn(y.z*XSCL, y.w*XSCL);
        float yy = y.x*y.x + y.y*y.y + y.z*y.z + y.w*y.w;
        #pragma unroll
        for (int o=8;o;o>>=1) yy += __shfl_xor_sync(~0u,yy,o);
        if ((l&15)==0){
            int hd2 = 2*i + (l>>4);
            g_diag[(bb*Hq+hd2)*Nq + n] = 0.0625f * yy;
        }
    }
}

// ---------------- LN2: warp-per-token, half out ----------------
__global__ void k_ln2(const float* __restrict__ g, const float* __restrict__ b) {
    int warp = (blockIdx.x*256 + threadIdx.x) >> 5;
    int l = threadIdx.x & 31;
    const float4* xr = (const float4*)(g_x1 + (size_t)warp*Eq);
    float4 v[6];
    float s1 = 0.f, s2 = 0.f;
    #pragma unroll
    for (int i=0;i<6;i++){
        v[i] = xr[l + 32*i];
        s1 += v[i].x+v[i].y+v[i].z+v[i].w;
        s2 += v[i].x*v[i].x+v[i].y*v[i].y+v[i].z*v[i].z+v[i].w*v[i].w;
    }
    #pragma unroll
    for (int o=16;o;o>>=1){ s1+=__shfl_xor_sync(~0u,s1,o); s2+=__shfl_xor_sync(~0u,s2,o); }
    float m = s1*(1.f/Eq);
    float rstd = rsqrtf(s2*(1.f/Eq) - m*m + 1e-5f);
    __half* hr = g_h2h + (size_t)warp*Eq;
    #pragma unroll
    for (int i=0;i<6;i++){
        int f = l + 32*i;
        float4 gv = ((const float4*)g)[f];
        float4 bv = ((const float4*)b)[f];
        float4 y;
        y.x = (v[i].x-m)*rstd*gv.x + bv.x;
        y.y = (v[i].y-m)*rstd*gv.y + bv.y;
        y.z = (v[i].z-m)*rstd*gv.z + bv.z;
        y.w = (v[i].w-m)*rstd*gv.w + bv.w;
        *(__half2*)&hr[f*4]   = __floats2half2_rn(y.x, y.y);
        *(__half2*)&hr[f*4+2] = __floats2half2_rn(y.z, y.w);
    }
}

__global__ void k_roundproj(const float* __restrict__ proj) {
    int i = blockIdx.x*256 + threadIdx.x;
    g_projh[i] = __float2half(proj[i]);
}

// ---------------- row max (stab_q) over half u ----------------
__global__ void k_stabq() {
    int row = blockIdx.x*8 + (threadIdx.x>>5);
    int l = threadIdx.x & 31;
    const __half2* u2 = (const __half2*)(g_uh + (size_t)row*256);
    __half2 m2 = u2[l*4];
    m2 = __hmax2(m2, u2[l*4+1]);
    m2 = __hmax2(m2, u2[l*4+2]);
    m2 = __hmax2(m2, u2[l*4+3]);
    float m = fmaxf(__low2float(m2), __high2float(m2));
    #pragma unroll
    for (int o=16;o;o>>=1) m = fmaxf(m, __shfl_xor_sync(~0u,m,o));
    if (l==0) g_stabq[row] = m;
}

// ---------------- merged: per-head max + per-row scale ----------------
__global__ void k_stabk_scale() {
    int g = blockIdx.x, tid = threadIdx.x;   // 48 blocks, 256 threads
    __shared__ float red[8];
    __shared__ float sk;
    float sq[8];
    float m = -1e30f;
    #pragma unroll
    for (int j=0;j<8;j++){ sq[j] = g_stabq[g*2048 + tid + j*256]; m = fmaxf(m, sq[j]); }
    #pragma unroll
    for (int o=16;o;o>>=1) m = fmaxf(m, __shfl_xor_sync(~0u,m,o));
    if ((tid&31)==0) red[tid>>5] = m;
    __syncthreads();
    if (tid==0){
        float t = red[0];
        #pragma unroll
        for (int i=1;i<8;i++) t = fmaxf(t, red[i]);
        sk = t;
    }
    __syncthreads();
    float s = sk;
    #pragma unroll
    for (int j=0;j<8;j++)
        g_scale[g*2048 + tid + j*256] = RATIO * __expf(sq[j] - s);
}

// ---------------- qp (half) + kp^T (half, transposed) from half u, one pass ----------------
__global__ void k_qk_exp() {
    __shared__ float t[32][33];
    int g = blockIdx.z, m0 = blockIdx.x*32, n0 = blockIdx.y*32;
    int x = threadIdx.x, y = threadIdx.y;   // block (32,8)
    #pragma unroll
    for (int i=0;i<32;i+=8){
        int n = n0 + y + i;
        size_t ro = ((size_t)g*2048 + n)*256;
        float uv = __half2float(g_uh[ro + m0 + x]);
        float dg = g_diag[g*2048+n], sq = g_stabq[g*2048+n], sc = g_scale[g*2048+n];
        float e = __expf(uv - dg - sq);
        g_qph[ro + m0 + x] = __float2half(fmaf(e, RATIO, REPS));
        t[y+i][x] = fmaf(e, sc, REPS);            // kv at [n_loc][m_loc]
    }
    __syncthreads();
    #pragma unroll
    for (int i=0;i<32;i+=8){
        int m = m0 + y + i;
        g_kphT[((size_t)g*256 + m)*2048 + n0 + x] = __float2half(t[x][y+i]);
    }
}

// ---------------- hTh: per head [128 x 2048]: rows 0-63 = hsh^T ----------------
__global__ void k_hT() {
    __shared__ __half t[32][33];
    int g = blockIdx.z, d0 = blockIdx.x*32, n0 = blockIdx.y*32;
    int x = threadIdx.x, y = threadIdx.y;   // block (32,8)
    #pragma unroll
    for (int i=0;i<32;i+=8)
        t[y+i][x] = g_hsh[((size_t)g*2048 + n0+y+i)*64 + d0 + x];
    __syncthreads();
    #pragma unroll
    for (int i=0;i<32;i+=8)
        g_hTh[(size_t)g*128*2048 + (size_t)(d0+y+i)*2048 + n0 + x] = t[x][y+i];
}
// row 64 = ones (rows 65-127 stay zero from static initialization, never written)
__global__ void k_hT2() {
    int g = blockIdx.x;
    __half* base = g_hTh + (size_t)g*128*2048 + (size_t)64*2048;
    __half2 one2 = __floats2half2_rn(1.f, 1.f);
    #pragma unroll
    for (int c = threadIdx.x; c < 1024; c += 256)
        *(__half2*)&base[c*2] = one2;
}

// ---------------- ctxf partial sums -> ctxTh (half [d][m], scaled) ----------------
__global__ void k_ctx2half() {
    __shared__ float t[32][33];
    int g = blockIdx.z, m0 = blockIdx.y*32, d0 = blockIdx.x*32;
    int x = threadIdx.x, y = threadIdx.y;   // block (32,8)
    #pragma unroll
    for (int i=0;i<32;i+=8){
        size_t base = (size_t)g*256*128 + (size_t)(m0+y+i)*128 + d0 + x;
        float v = g_ctxf[base];
        #pragma unroll
        for (int s=1;s<CTX_S;s++) v += g_ctxf[base + (size_t)s*CH];
        t[y+i][x] = v;   // [m_loc][d_loc]
    }
    __syncthreads();
    #pragma unroll
    for (int i=0;i<32;i+=8){
        int d = d0 + y + i;
        float v = t[x][y+i];
        if (d < 64) v *= (1.0f/XSCL);
        g_ctxTh[(size_t)g*128*256 + (size_t)d*256 + m0 + x] = __float2half(v);
    }
}

// ---------------- transpose weights to half ----------------
__global__ void k_transposeh(const float* __restrict__ in, __half* __restrict__ out,
                             int R, int C) {
    __shared__ float t[32][33];
    int bx = blockIdx.x*32, by = blockIdx.y*32;
    int x = threadIdx.x, y = threadIdx.y;
    #pragma unroll
    for (int i=0;i<32;i+=8)
        t[y+i][x] = in[(size_t)(by+y+i)*C + bx+x];
    __syncthreads();
    #pragma unroll
    for (int i=0;i<32;i+=8)
        out[(size_t)(bx+y+i)*R + by+x] = __float2half(t[x][y+i]);
}

// ================= f16 mma.sync GEMM (ldmatrix, 3-stage, 1 sync/iter) =================
// EPI 0: Ch=half(gelu(acc+bias)). EPI 1: C=acc+bias+resid. EPI 2: Ch=half(acc).
// EPI 3: attention: col 64 = denom; C = resid + num/den.
// EPI 6: ctx split-K: plain store into partial buffer C[chunk][head][m][128].
#define STB 80                        // smem row stride bytes (40 halves)
#define STAGE_A 10240                 // 128 rows * 80 B
#define STAGE   (2*STAGE_A)           // 20480
#define GSMEM_BYTES (3*STAGE)         // 61440 B

template<int EPI>
__global__ __launch_bounds__(256, 2) void k_gemm_h(
        const __half* __restrict__ A, int lda, size_t strA,
        const __half* __restrict__ Bt, int ldb, size_t strB,
        int klen,
        const float* __restrict__ bias,
        const float* __restrict__ resid,
        float* __restrict__ C, __half* __restrict__ Ch, int ldc) {
    extern __shared__ __align__(16) char dsm[];
    uint32_t smb = s2u(dsm);
    int tid = threadIdx.x, wid = tid>>5, lane = tid&31;
    int wm = (wid&1)*64, wn = (wid>>1)*32;
    int r = lane>>2, cq = lane&3;
    int z = blockIdx.z;
    int zh = z, zc = 0;
    if (EPI == 6){ zh = z>>2; zc = z&3; }

    int rbase = blockIdx.y*128, cbase = (EPI==6) ? 0 : blockIdx.x*128;
    const __half* Ag = A  + zh*strA + (size_t)zc*klen + (size_t)rbase*lda;
    const __half* Bg = Bt + zh*strB + (size_t)zc*klen + (size_t)cbase*ldb;
    int KT = klen >> 5;

    uint32_t a_ldsm_base = (uint32_t)((wm + (lane&7) + ((lane>>3)&1)*8)*STB + ((lane>>4)&1)*16);
    uint32_t b_ldsm_base = (uint32_t)((wn + (lane&7) + ((lane>>4)&1)*8)*STB + ((lane>>3)&1)*16);

    float acc[4][4][4];
    #pragma unroll
    for (int i=0;i<4;i++)
        #pragma unroll
        for (int j=0;j<4;j++)
            #pragma unroll
            for (int k=0;k<4;k++) acc[i][j][k]=0.f;

    #define LOAD_STAGE(s, kt) do { \
        uint32_t _ab = smb + (uint32_t)((s)*STAGE); \
        uint32_t _bb = _ab + STAGE_A; \
        const __half* _Ag = Ag + (kt)*32; \
        const __half* _Bg = Bg + (kt)*32; \
        _Pragma("unroll") \
        for (int _t=0;_t<2;_t++){ \
            int _q = tid + _t*256; int _r = _q>>2, _c = _q&3; \
            cpasync16(_ab + (uint32_t)(_r*STB + _c*16), _Ag + (size_t)_r*lda + _c*8); \
            cpasync16(_bb + (uint32_t)(_r*STB + _c*16), _Bg + (size_t)_r*ldb + _c*8); \
        } \
        asm volatile("cp.async.commit_group;" ::: "memory"); \
    } while(0)

    LOAD_STAGE(0, 0);
    if (KT > 1) LOAD_STAGE(1, 1);
    int cur = 0;
    for (int kt=0; kt<KT; kt++){
        if (kt+1 < KT) asm volatile("cp.async.wait_group 1;" ::: "memory");
        else           asm volatile("cp.async.wait_group 0;" ::: "memory");
        __syncthreads();
        if (kt+2 < KT){
            int nxt = cur+2; if (nxt>=3) nxt-=3;
            LOAD_STAGE(nxt, kt+2);
        }
        uint32_t ab = smb + (uint32_t)(cur*STAGE) + a_ldsm_base;
        uint32_t bb = smb + (uint32_t)(cur*STAGE) + STAGE_A + b_ldsm_base;
        #pragma unroll
        for (int ks=0; ks<2; ks++){
            uint32_t a[4][4], b[2][4];
            #pragma unroll
            for (int mf=0; mf<4; mf++)
                LDSM4(a[mf][0],a[mf][1],a[mf][2],a[mf][3], ab + mf*16*STB + ks*32);
            #pragma unroll
            for (int p=0; p<2; p++)
                LDSM4(b[p][0],b[p][1],b[p][2],b[p][3], bb + p*16*STB + ks*32);
            #pragma unroll
            for (int mf=0; mf<4; mf++)
                #pragma unroll
                for (int nf=0; nf<4; nf++)
                    mma16(acc[mf][nf], a[mf], &b[nf>>1][(nf&1)*2]);
        }
        cur = (cur==2) ? 0 : cur+1;
    }
    #undef LOAD_STAGE

    // Epilogue: two 64-row halves staged through smem (stride 132)
    float* stg = (float*)dsm;
    #pragma unroll 1
    for (int h=0; h<2; h++){
        __syncthreads();
        if ((wid&1) == h){
            #pragma unroll
            for (int mf=0; mf<4; mf++)
                #pragma unroll
                for (int nf=0; nf<4; nf++){
                    int row = mf*16 + r, col = wn + nf*8 + 2*cq;
                    *(float2*)&stg[row*132 + col]     = make_float2(acc[mf][nf][0], acc[mf][nf][1]);
                    *(float2*)&stg[(row+8)*132 + col] = make_float2(acc[mf][nf][2], acc[mf][nf][3]);
                }
        }
        __syncthreads();
        #pragma unroll
        for (int t=0;t<8;t++){
            int q = tid + t*256; int row = q>>5, c4 = (q&31)*4;
            int col = cbase + c4;
            if (EPI == 3){
                if (c4 < 64){
                    float4 v = *(const float4*)&stg[row*132 + c4];
                    float dinv = 1.f / stg[row*132 + 64];
                    int bb2 = zh/12, hd = zh%12;
                    int n = rbase + h*64 + row;
                    size_t oi = ((size_t)(bb2*2048 + n))*768 + hd*64 + c4;
                    float4 rv = *(const float4*)&resid[oi];
                    v.x = rv.x + v.x*dinv; v.y = rv.y + v.y*dinv;
                    v.z = rv.z + v.z*dinv; v.w = rv.w + v.w*dinv;
                    *(float4*)&C[oi] = v;
                }
            } else if (EPI == 6){
                float4 v = *(const float4*)&stg[row*132 + c4];
                size_t oi = (size_t)zc*CH + (size_t)zh*256*128 + (size_t)(rbase + h*64 + row)*128 + c4;
                *(float4*)&C[oi] = v;
            } else if (EPI == 2){
                float4 v = *(const float4*)&stg[row*132 + c4];
                size_t oi = (size_t)(rbase + h*64 + row)*ldc + col;
                *reinterpret_cast<__half2*>(Ch + oi)     = __floats2half2_rn(v.x, v.y);
                *reinterpret_cast<__half2*>(Ch + oi + 2) = __floats2half2_rn(v.z, v.w);
            } else {
                float4 v = *(const float4*)&stg[row*132 + c4];
                size_t oi = (size_t)(rbase + h*64 + row)*ldc + col;
                if (EPI == 0){
                    v.x += bias[col+0]; v.y += bias[col+1]; v.z += bias[col+2]; v.w += bias[col+3];
                    v.x = 0.5f*v.x*(1.f+erff(v.x*0.70710678118654752f));
                    v.y = 0.5f*v.y*(1.f+erff(v.y*0.70710678118654752f));
                    v.z = 0.5f*v.z*(1.f+erff(v.z*0.70710678118654752f));
                    v.w = 0.5f*v.w*(1.f+erff(v.w*0.70710678118654752f));
                    *reinterpret_cast<__half2*>(Ch + oi)     = __floats2half2_rn(v.x, v.y);
                    *reinterpret_cast<__half2*>(Ch + oi + 2) = __floats2half2_rn(v.z, v.w);
                } else {
                    float4 rv = *(const float4*)&resid[oi];
                    v.x += bias[col+0] + rv.x; v.y += bias[col+1] + rv.y;
                    v.z += bias[col+2] + rv.z; v.w += bias[col+3] + rv.w;
                    *(float4*)&C[oi] = v;
                }
            }
        }
    }
}

extern "C" void kernel_launch(void* const* d_in, const int* in_sizes, int n_in,
                              void* d_out, int out_size) {
    const float* x    = (const float*)d_in[0];
    const float* proj = (const float*)d_in[1];
    const float* ln1g = (const float*)d_in[2];
    const float* ln1b = (const float*)d_in[3];
    const float* ln2g = (const float*)d_in[4];
    const float* ln2b = (const float*)d_in[5];
    const float* W1   = (const float*)d_in[6];
    const float* b1   = (const float*)d_in[7];
    const float* W2   = (const float*)d_in[8];
    const float* b2   = (const float*)d_in[9];
    float* out = (float*)d_out;

    cudaFuncSetAttribute(k_gemm_h<0>, cudaFuncAttributeMaxDynamicSharedMemorySize, GSMEM_BYTES);
    cudaFuncSetAttribute(k_gemm_h<1>, cudaFuncAttributeMaxDynamicSharedMemorySize, GSMEM_BYTES);
    cudaFuncSetAttribute(k_gemm_h<2>, cudaFuncAttributeMaxDynamicSharedMemorySize, GSMEM_BYTES);
    cudaFuncSetAttribute(k_gemm_h<3>, cudaFuncAttributeMaxDynamicSharedMemorySize, GSMEM_BYTES);
    cudaFuncSetAttribute(k_gemm_h<6>, cudaFuncAttributeMaxDynamicSharedMemorySize, GSMEM_BYTES);

    __half* w1h;  cudaGetSymbolAddress((void**)&w1h,  g_w1h);
    __half* w2h;  cudaGetSymbolAddress((void**)&w2h,  g_w2h);
    __half* h2h;  cudaGetSymbolAddress((void**)&h2h,  g_h2h);
    __half* midh; cudaGetSymbolAddress((void**)&midh, g_midh);
    __half* hsh;  cudaGetSymbolAddress((void**)&hsh,  g_hsh);
    __half* prjh; cudaGetSymbolAddress((void**)&prjh, g_projh);
    __half* qph;  cudaGetSymbolAddress((void**)&qph,  g_qph);
    __half* kpht; cudaGetSymbolAddress((void**)&kpht, g_kphT);
    __half* hth;  cudaGetSymbolAddress((void**)&hth,  g_hTh);
    __half* ctxh; cudaGetSymbolAddress((void**)&ctxh, g_ctxTh);
    __half* uh;   cudaGetSymbolAddress((void**)&uh,   g_uh);
    float* ctxf;  cudaGetSymbolAddress((void**)&ctxf, g_ctxf);
    float* x1;    cudaGetSymbolAddress((void**)&x1,   g_x1);

    // input-only prep
    k_transposeh<<<dim3(Fq/32, Eq/32), dim3(32,8)>>>(W1, w1h, Eq, Fq);
    k_transposeh<<<dim3(Eq/32, Fq/32), dim3(32,8)>>>(W2, w2h, Fq, Eq);
    k_roundproj<<<Mq*Dhq/256, 256>>>(proj);

    k_ln1<<<BN/8, 256>>>(x, ln1g, ln1b);
    // u = hsh @ projh^T : [98304 x 64] @ [64 x 256] -> half u
    k_gemm_h<2><<<dim3(Mq/128, ROWS/128), 256, GSMEM_BYTES>>>(
        hsh, Dhq, 0, prjh, Dhq, 0, Dhq, nullptr, nullptr, nullptr, uh, Mq);
    k_stabq<<<ROWS/8, 256>>>();
    k_stabk_scale<<<Bq*Hq, 256>>>();
    k_qk_exp<<<dim3(Mq/32, Nq/32, Bq*Hq), dim3(32,8)>>>();
    k_hT<<<dim3(2, Nq/32, Bq*Hq), dim3(32,8)>>>();
    k_hT2<<<Bq*Hq, 256>>>();
    // ctx GEMM split-K=4, disjoint partials: per head [256 x 2048] @ [2048 x 128]
    k_gemm_h<6><<<dim3(1, 2, Bq*Hq*CTX_S), 256, GSMEM_BYTES>>>(
        kpht, Nq, (size_t)Mq*Nq, hth, Nq, (size_t)128*Nq, Nq/CTX_S, nullptr, nullptr, ctxf, nullptr, 0);
    k_ctx2half<<<dim3(4, 8, Bq*Hq), dim3(32,8)>>>();
    // attn: per head [2048 x 256] @ [256 x 128(ctx^T|ksum)] -> x1 = x + num/den
    k_gemm_h<3><<<dim3(1, Nq/128, Bq*Hq), 256, GSMEM_BYTES>>>(
        qph, Mq, (size_t)Nq*Mq, ctxh, Mq, (size_t)128*Mq, Mq, nullptr, x, x1, nullptr, 0);
    k_ln2<<<BN/8, 256>>>(ln2g, ln2b);

    // MLP GEMM1: [8192x768]@[768x3072] -> midh (gelu, half)
    k_gemm_h<0><<<dim3(Fq/128, BN/128), 256, GSMEM_BYTES>>>(
        h2h, Eq, 0, w1h, Eq, 0, Eq, b1, nullptr, nullptr, midh, Fq);
    // MLP GEMM2: [8192x3072]@[3072x768] + bias + x1 -> out (full-K)
    k_gemm_h<1><<<dim3(Eq/128, BN/128), 256, GSMEM_BYTES>>>(
        midh, Fq, 0, w2h, Fq, 0, Fq, b2, x1, out, nullptr, Eq);
}